// round 1
// baseline (speedup 1.0000x reference)
#include <cuda_runtime.h>
#include <cuda_bf16.h>
#include <cstdint>

#define B_  2
#define S_  2048
#define H_  2048
#define NH_ 16
#define HD_ 128
#define M_  (B_*S_)            // 4096
#define SCALE_ 0.08838834764831845f   // 128^-0.5

// ---------------- scratch (device globals: no allocation allowed) ----------
__device__ float g_q[(size_t)B_*NH_*S_*HD_];     // [b,h,s,d]
__device__ float g_k[(size_t)B_*NH_*S_*HD_];
__device__ float g_v[(size_t)B_*NH_*S_*HD_];
__device__ float g_ctx[(size_t)B_*S_*H_];        // [b,s,h*HD+d]

typedef unsigned long long ull;

// ---------------- packed fp32x2 helpers (Blackwell FFMA2 path) -------------
__device__ __forceinline__ ull pack2(float x) {
    ull r; unsigned u = __float_as_uint(x);
    asm("mov.b64 %0, {%1, %1};" : "=l"(r) : "r"(u));
    return r;
}
__device__ __forceinline__ ull packxy(float x, float y) {
    ull r; unsigned ux = __float_as_uint(x), uy = __float_as_uint(y);
    asm("mov.b64 %0, {%1, %2};" : "=l"(r) : "r"(ux), "r"(uy));
    return r;
}
__device__ __forceinline__ void unpack2(ull v, float &x, float &y) {
    unsigned lo, hi;
    asm("mov.b64 {%0, %1}, %2;" : "=r"(lo), "=r"(hi) : "l"(v));
    x = __uint_as_float(lo); y = __uint_as_float(hi);
}
__device__ __forceinline__ void ffma2(ull &d, ull a, ull b) {
    asm("fma.rn.f32x2 %0, %1, %2, %0;" : "+l"(d) : "l"(a), "l"(b));
}
__device__ __forceinline__ ull mul2(ull a, ull b) {
    ull d; asm("mul.rn.f32x2 %0, %1, %2;" : "=l"(d) : "l"(a), "l"(b));
    return d;
}

// ---------------- SGEMM: C[m,n] = sum_k A[m,k] * W[n,k] --------------------
// Both operands K-major. 128x128 tile, BK=16, 256 threads, 8x8 microtile
// computed as 8 x 4 f32x2 pairs. MODE 0: C[m*H + n]. MODE 1: scatter to
// [b,h,s,d] head-major layout.
template<int MODE>
__device__ __forceinline__ void gemm_body(const float* __restrict__ A,
                                          const float* __restrict__ W,
                                          float* __restrict__ C)
{
    const int K = H_;
    const int N = H_;
    __shared__ float As[16][128];
    __shared__ float Bs[16][128];

    int tid = threadIdx.x;
    int mb = blockIdx.y * 128;
    int nb = blockIdx.x * 128;
    int ty = tid >> 4;           // 0..15
    int tx = tid & 15;           // 0..15

    ull acc[8][4];
#pragma unroll
    for (int i = 0; i < 8; i++)
#pragma unroll
        for (int j = 0; j < 4; j++) acc[i][j] = 0ull;

    int lr = tid >> 2;           // 0..63
    int lc = (tid & 3) * 4;      // 0,4,8,12
    const float* Ap0 = A + (size_t)(mb + lr)      * K + lc;
    const float* Ap1 = A + (size_t)(mb + 64 + lr) * K + lc;
    const float* Wp0 = W + (size_t)(nb + lr)      * K + lc;
    const float* Wp1 = W + (size_t)(nb + 64 + lr) * K + lc;

    for (int kb = 0; kb < K; kb += 16) {
        float4 a0 = *(const float4*)(Ap0 + kb);
        float4 a1 = *(const float4*)(Ap1 + kb);
        float4 b0 = *(const float4*)(Wp0 + kb);
        float4 b1 = *(const float4*)(Wp1 + kb);
        As[lc+0][lr]    = a0.x; As[lc+1][lr]    = a0.y; As[lc+2][lr]    = a0.z; As[lc+3][lr]    = a0.w;
        As[lc+0][64+lr] = a1.x; As[lc+1][64+lr] = a1.y; As[lc+2][64+lr] = a1.z; As[lc+3][64+lr] = a1.w;
        Bs[lc+0][lr]    = b0.x; Bs[lc+1][lr]    = b0.y; Bs[lc+2][lr]    = b0.z; Bs[lc+3][lr]    = b0.w;
        Bs[lc+0][64+lr] = b1.x; Bs[lc+1][64+lr] = b1.y; Bs[lc+2][64+lr] = b1.z; Bs[lc+3][64+lr] = b1.w;
        __syncthreads();
#pragma unroll
        for (int k = 0; k < 16; k++) {
            float4 av0 = *(const float4*)&As[k][ty*4];
            float4 av1 = *(const float4*)&As[k][64 + ty*4];
            float4 bv0 = *(const float4*)&Bs[k][tx*4];
            float4 bv1 = *(const float4*)&Bs[k][64 + tx*4];
            ull bp[4];
            bp[0] = packxy(bv0.x, bv0.y);
            bp[1] = packxy(bv0.z, bv0.w);
            bp[2] = packxy(bv1.x, bv1.y);
            bp[3] = packxy(bv1.z, bv1.w);
            float ar[8] = {av0.x, av0.y, av0.z, av0.w, av1.x, av1.y, av1.z, av1.w};
#pragma unroll
            for (int i = 0; i < 8; i++) {
                ull ap = pack2(ar[i]);
#pragma unroll
                for (int j = 0; j < 4; j++) ffma2(acc[i][j], ap, bp[j]);
            }
        }
        __syncthreads();
    }

#pragma unroll
    for (int i = 0; i < 8; i++) {
        int m = mb + (i < 4 ? ty*4 + i : 64 + ty*4 + (i - 4));
#pragma unroll
        for (int j = 0; j < 4; j++) {
            float lo, hi; unpack2(acc[i][j], lo, hi);
            int n0 = nb + (j < 2 ? tx*4 + j*2 : 64 + tx*4 + (j - 2)*2);
            if (MODE == 0) {
                *(float2*)&C[(size_t)m * N + n0] = make_float2(lo, hi);
            } else {
                int b = m >> 11, s = m & (S_ - 1);
                int h = n0 >> 7, d = n0 & (HD_ - 1);
                size_t base = (((size_t)(b*NH_ + h)) * S_ + s) * HD_ + d;
                *(float2*)&C[base] = make_float2(lo, hi);
            }
        }
    }
}

__global__ void __launch_bounds__(256) k_proj_q(const float* __restrict__ X, const float* __restrict__ W) { gemm_body<1>(X, W, g_q); }
__global__ void __launch_bounds__(256) k_proj_k(const float* __restrict__ X, const float* __restrict__ W) { gemm_body<1>(X, W, g_k); }
__global__ void __launch_bounds__(256) k_proj_v(const float* __restrict__ X, const float* __restrict__ W) { gemm_body<1>(X, W, g_v); }
__global__ void __launch_bounds__(256) k_out_proj(const float* __restrict__ W, float* __restrict__ C) { gemm_body<0>(g_ctx, W, C); }

// ---------------- RoPE (in place on g_q, g_k) ------------------------------
__global__ void k_rope(const float* __restrict__ cosp, const float* __restrict__ sinp)
{
    int idx = blockIdx.x * blockDim.x + threadIdx.x;   // B*NH*S*64 threads
    int d  = idx & 63;
    int s  = (idx >> 6) & (S_ - 1);
    int bh = idx >> 17;
    size_t base = ((size_t)bh * S_ + s) * HD_;
    float c1 = cosp[s*HD_ + d],      s1 = sinp[s*HD_ + d];
    float c2 = cosp[s*HD_ + d + 64], s2 = sinp[s*HD_ + d + 64];
    float x1 = g_q[base + d], x2 = g_q[base + d + 64];
    g_q[base + d]      = x1*c1 - x2*s1;
    g_q[base + d + 64] = x2*c2 + x1*s2;
    x1 = g_k[base + d]; x2 = g_k[base + d + 64];
    g_k[base + d]      = x1*c1 - x2*s1;
    g_k[base + d + 64] = x2*c2 + x1*s2;
}

// ---------------- causal flash attention -----------------------------------
// BQ = BK = 64, 256 threads. Thread (i = tid>>2, c = tid&3) owns q-row i and
// d = 8*t + 2*c + {0,1} (t = 0..15): smem reads in the inner loops are
// 4-distinct-address broadcasts (conflict-free) and 8B-vector loads.
__global__ void __launch_bounds__(256) k_flash()
{
    __shared__ float Ts[64 * 128];        // 32 KB: holds K tile, then V tile
    int tid = threadIdx.x;
    int i = tid >> 2;                     // 0..63 q-row in tile
    int c = tid & 3;                      // 0..3
    int qt = blockIdx.x;                  // 0..31 q tile
    int bh = blockIdx.y;                  // 0..31
    int b = bh >> 4, h = bh & (NH_ - 1);
    size_t base = (size_t)bh * S_ * HD_;
    int qg = qt * 64 + i;

    ull qf[16];
    {
        const float* qrow = g_q + base + (size_t)qg * HD_ + 2*c;
        ull sc2 = pack2(SCALE_);
#pragma unroll
        for (int t = 0; t < 16; t++)
            qf[t] = mul2(*(const ull*)(qrow + 8*t), sc2);
    }
    ull o[16];
#pragma unroll
    for (int t = 0; t < 16; t++) o[t] = 0ull;
    float mcur = -1e30f, l = 0.f;

    for (int kt = 0; kt <= qt; kt++) {
        // --- stage K tile ---
        const float* kptr = g_k + base + (size_t)kt * 64 * HD_;
        __syncthreads();
#pragma unroll
        for (int r = 0; r < 8; r++) {
            int f = tid + 256 * r;
            *(float4*)&Ts[f*4] = *(const float4*)(kptr + f*4);
        }
        __syncthreads();
        // --- scores ---
        float s[64];
#pragma unroll
        for (int j = 0; j < 64; j++) {
            ull a = 0ull;
            const float* kr = &Ts[j*128 + 2*c];
#pragma unroll
            for (int t = 0; t < 16; t++) ffma2(a, qf[t], *(const ull*)(kr + 8*t));
            float lo, hi; unpack2(a, lo, hi);
            float p = lo + hi;
            p += __shfl_xor_sync(0xffffffffu, p, 1);
            p += __shfl_xor_sync(0xffffffffu, p, 2);
            s[j] = p;
        }
        if (kt == qt) {
#pragma unroll
            for (int j = 0; j < 64; j++) if (j > i) s[j] = -1e30f;
        }
        // --- online softmax rescale ---
        float mnew = mcur;
#pragma unroll
        for (int j = 0; j < 64; j++) mnew = fmaxf(mnew, s[j]);
        float corr = __expf(mcur - mnew);
        mcur = mnew;
        l *= corr;
        ull corr2 = pack2(corr);
#pragma unroll
        for (int t = 0; t < 16; t++) o[t] = mul2(o[t], corr2);
        // --- stage V tile (reuse buffer) ---
        const float* vptr = g_v + base + (size_t)kt * 64 * HD_;
        __syncthreads();
#pragma unroll
        for (int r = 0; r < 8; r++) {
            int f = tid + 256 * r;
            *(float4*)&Ts[f*4] = *(const float4*)(vptr + f*4);
        }
        __syncthreads();
        // --- accumulate P @ V ---
#pragma unroll
        for (int j = 0; j < 64; j++) {
            float p = __expf(s[j] - mcur);
            l += p;
            ull p2 = pack2(p);
            const float* vr = &Ts[j*128 + 2*c];
#pragma unroll
            for (int t = 0; t < 16; t++) ffma2(o[t], p2, *(const ull*)(vr + 8*t));
        }
    }

    float inv = 1.f / l;
    float* orow = g_ctx + ((size_t)b * S_ + qg) * H_ + h * HD_ + 2*c;
#pragma unroll
    for (int t = 0; t < 16; t++) {
        float lo, hi; unpack2(o[t], lo, hi);
        *(float2*)(orow + 8*t) = make_float2(lo * inv, hi * inv);
    }
}

// ---------------- launch ---------------------------------------------------
extern "C" void kernel_launch(void* const* d_in, const int* in_sizes, int n_in,
                              void* d_out, int out_size)
{
    const float* X   = (const float*)d_in[0];
    const float* cp  = (const float*)d_in[1];
    const float* sp  = (const float*)d_in[2];
    const float* Wq  = (const float*)d_in[3];
    const float* Wk  = (const float*)d_in[4];
    const float* Wv  = (const float*)d_in[5];
    const float* Wo  = (const float*)d_in[6];
    float* out = (float*)d_out;

    dim3 gg(H_ / 128, M_ / 128);           // (16, 32)
    k_proj_q<<<gg, 256>>>(X, Wq);
    k_proj_k<<<gg, 256>>>(X, Wk);
    k_proj_v<<<gg, 256>>>(X, Wv);

    int total = B_ * NH_ * S_ * 64;        // 4,194,304
    k_rope<<<total / 256, 256>>>(cp, sp);

    k_flash<<<dim3(S_ / 64, B_ * NH_), 256>>>();

    k_out_proj<<<gg, 256>>>(Wo, out);
}

// round 3
// speedup vs baseline: 1.5648x; 1.5648x over previous
#include <cuda_runtime.h>
#include <cuda_bf16.h>
#include <cstdint>

#define B_  2
#define S_  2048
#define H_  2048
#define NH_ 16
#define HD_ 128
#define M_  (B_*S_)            // 4096
#define SCALE_ 0.08838834764831845f   // 128^-0.5

// ---------------- scratch (device globals: no allocation allowed) ----------
__device__ float g_q[(size_t)B_*NH_*S_*HD_];     // [b,h,s,d]
__device__ float g_k[(size_t)B_*NH_*S_*HD_];
__device__ float g_v[(size_t)B_*NH_*S_*HD_];
__device__ float g_ctx[(size_t)B_*S_*H_];        // [b,s,h*HD+d]

typedef unsigned long long ull;

// ---------------- packed fp32x2 helpers (flash path) -----------------------
__device__ __forceinline__ ull pack2(float x) {
    ull r; unsigned u = __float_as_uint(x);
    asm("mov.b64 %0, {%1, %1};" : "=l"(r) : "r"(u));
    return r;
}
__device__ __forceinline__ void unpack2(ull v, float &x, float &y) {
    unsigned lo, hi;
    asm("mov.b64 {%0, %1}, %2;" : "=r"(lo), "=r"(hi) : "l"(v));
    x = __uint_as_float(lo); y = __uint_as_float(hi);
}
__device__ __forceinline__ void ffma2(ull &d, ull a, ull b) {
    asm("fma.rn.f32x2 %0, %1, %2, %0;" : "+l"(d) : "l"(a), "l"(b));
}
__device__ __forceinline__ ull mul2(ull a, ull b) {
    ull d; asm("mul.rn.f32x2 %0, %1, %2;" : "=l"(d) : "l"(a), "l"(b));
    return d;
}

// ---------------- tf32 helpers ---------------------------------------------
__device__ __forceinline__ unsigned tf32_of(float f) {
    unsigned r; asm("cvt.rn.tf32.f32 %0, %1;" : "=r"(r) : "f"(f)); return r;
}
__device__ __forceinline__ uint4 cvt4(float4 v) {
    uint4 o; o.x = tf32_of(v.x); o.y = tf32_of(v.y); o.z = tf32_of(v.z); o.w = tf32_of(v.w);
    return o;
}
__device__ __forceinline__ void mma_tf32(float c[4], const unsigned a[4], const unsigned b[2]) {
    asm volatile(
        "mma.sync.aligned.m16n8k8.row.col.f32.tf32.tf32.f32 "
        "{%0,%1,%2,%3}, {%4,%5,%6,%7}, {%8,%9}, {%0,%1,%2,%3};"
        : "+f"(c[0]), "+f"(c[1]), "+f"(c[2]), "+f"(c[3])
        : "r"(a[0]), "r"(a[1]), "r"(a[2]), "r"(a[3]), "r"(b[0]), "r"(b[1]));
}

// ======================= tf32 mma.sync GEMM ================================
// C[m,n] = sum_k A[m,k] * W[n,k]. CTA tile 128x128, BK=16, 256 threads.
// Warp grid 2(m) x 4(n): warp tile 64x32 -> mfrag 4 (m16), nfrag 4 (n8).
// Smem rows strided by 20 floats: fragment LDS bank = (20g + r) mod 32 is a
// bijection over the 32 lanes -> conflict-free.
#define BK  16
#define STR 20

// MODE 0: C[m*H_ + n]   MODE 1: scatter to [b,h,s,d]
template<int MODE>
__device__ __forceinline__ void gemm_tc(const float* __restrict__ A,
                                        const float* __restrict__ W,
                                        float* __restrict__ Cdst,
                                        int mb, int nb)
{
    __shared__ float As[2][128*STR];
    __shared__ float Bs[2][128*STR];

    const int tid = threadIdx.x;
    const int wid = tid >> 5, lane = tid & 31;
    const int g = lane >> 2, r = lane & 3;
    const int wm = (wid >> 2) * 64;      // warp m offset (0 or 64)
    const int wn = (wid & 3) * 32;       // warp n offset (0,32,64,96)

    float c[4][4][4];
#pragma unroll
    for (int i = 0; i < 4; i++)
#pragma unroll
        for (int j = 0; j < 4; j++)
#pragma unroll
            for (int q = 0; q < 4; q++) c[i][j][q] = 0.f;

    const int lrow = tid >> 2;           // 0..63? no: 256 threads -> f mapping below
    (void)lrow;

    // chunk loader: 128 rows x 16 k per operand = 512 float4, 2 per thread
    float4 ra[2], rb[2];
    {
#pragma unroll
        for (int q = 0; q < 2; q++) {
            int f = tid + 256*q; int row = f >> 2, kq = f & 3;
            ra[q] = *(const float4*)(A + (size_t)(mb + row)*H_ + kq*4);
            rb[q] = *(const float4*)(W + (size_t)(nb + row)*H_ + kq*4);
        }
#pragma unroll
        for (int q = 0; q < 2; q++) {
            int f = tid + 256*q; int row = f >> 2, kq = f & 3;
            *(uint4*)&As[0][row*STR + kq*4] = cvt4(ra[q]);
            *(uint4*)&Bs[0][row*STR + kq*4] = cvt4(rb[q]);
        }
    }
    __syncthreads();

    const int NCH = H_ / BK;             // 128
    for (int ch = 0; ch < NCH; ch++) {
        int buf = ch & 1;
        if (ch + 1 < NCH) {
            int kb = (ch + 1) * BK;
#pragma unroll
            for (int q = 0; q < 2; q++) {
                int f = tid + 256*q; int row = f >> 2, kq = f & 3;
                ra[q] = *(const float4*)(A + (size_t)(mb + row)*H_ + kb + kq*4);
                rb[q] = *(const float4*)(W + (size_t)(nb + row)*H_ + kb + kq*4);
            }
        }
        const float* as = As[buf];
        const float* bs = Bs[buf];
#pragma unroll
        for (int ks = 0; ks < 2; ks++) {
            unsigned af[4][4], bf[4][2];
#pragma unroll
            for (int mf = 0; mf < 4; mf++) {
                const unsigned* ap = (const unsigned*)&as[(wm + mf*16 + g)*STR + ks*8 + r];
                af[mf][0] = ap[0];
                af[mf][1] = ap[8*STR];
                af[mf][2] = ap[4];
                af[mf][3] = ap[8*STR + 4];
            }
#pragma unroll
            for (int nf = 0; nf < 4; nf++) {
                const unsigned* bp = (const unsigned*)&bs[(wn + nf*8 + g)*STR + ks*8 + r];
                bf[nf][0] = bp[0];
                bf[nf][1] = bp[4];
            }
#pragma unroll
            for (int mf = 0; mf < 4; mf++)
#pragma unroll
                for (int nf = 0; nf < 4; nf++)
                    mma_tf32(c[mf][nf], af[mf], bf[nf]);
        }
        if (ch + 1 < NCH) {
#pragma unroll
            for (int q = 0; q < 2; q++) {
                int f = tid + 256*q; int row = f >> 2, kq = f & 3;
                *(uint4*)&As[buf ^ 1][row*STR + kq*4] = cvt4(ra[q]);
                *(uint4*)&Bs[buf ^ 1][row*STR + kq*4] = cvt4(rb[q]);
            }
            __syncthreads();
        }
    }

    // epilogue
#pragma unroll
    for (int mf = 0; mf < 4; mf++) {
#pragma unroll
        for (int nf = 0; nf < 4; nf++) {
            int mrow = mb + wm + mf*16 + g;
            int col  = nb + wn + nf*8 + r*2;
#pragma unroll
            for (int half = 0; half < 2; half++) {
                int m = mrow + half*8;
                float2 v = make_float2(c[mf][nf][half*2], c[mf][nf][half*2 + 1]);
                if (MODE == 0) {
                    *(float2*)&Cdst[(size_t)m*H_ + col] = v;
                } else {
                    int b = m >> 11, s = m & (S_ - 1);
                    int h = col >> 7, d0 = col & (HD_ - 1);
                    *(float2*)&Cdst[(((size_t)(b*NH_ + h))*S_ + s)*HD_ + d0] = v;
                }
            }
        }
    }
}

__global__ void __launch_bounds__(256) k_qkv_tc(const float* __restrict__ X,
                                                const float* __restrict__ Wq,
                                                const float* __restrict__ Wk,
                                                const float* __restrict__ Wv) {
    int which = blockIdx.x >> 4;                 // 0=q 1=k 2=v
    int nb = (blockIdx.x & 15) * 128;
    int mb = blockIdx.y * 128;
    const float* W = (which == 0) ? Wq : (which == 1) ? Wk : Wv;
    float* dst = (which == 0) ? g_q : (which == 1) ? g_k : g_v;
    gemm_tc<1>(X, W, dst, mb, nb);
}
__global__ void __launch_bounds__(256) k_out_tc(const float* __restrict__ Wo,
                                                float* __restrict__ C) {
    gemm_tc<0>(g_ctx, Wo, C, blockIdx.y * 128, blockIdx.x * 128);
}

// ---------------- RoPE (in place on g_q, g_k) ------------------------------
__global__ void k_rope(const float* __restrict__ cosp, const float* __restrict__ sinp)
{
    int idx = blockIdx.x * blockDim.x + threadIdx.x;   // B*NH*S*64 threads
    int d  = idx & 63;
    int s  = (idx >> 6) & (S_ - 1);
    int bh = idx >> 17;
    size_t base = ((size_t)bh * S_ + s) * HD_;
    float c1 = cosp[s*HD_ + d],      s1 = sinp[s*HD_ + d];
    float c2 = cosp[s*HD_ + d + 64], s2 = sinp[s*HD_ + d + 64];
    float x1 = g_q[base + d], x2 = g_q[base + d + 64];
    g_q[base + d]      = x1*c1 - x2*s1;
    g_q[base + d + 64] = x2*c2 + x1*s2;
    x1 = g_k[base + d]; x2 = g_k[base + d + 64];
    g_k[base + d]      = x1*c1 - x2*s1;
    g_k[base + d + 64] = x2*c2 + x1*s2;
}

// ---------------- causal flash attention (FFMA2) ---------------------------
__global__ void __launch_bounds__(256) k_flash()
{
    __shared__ float Ts[64 * 128];        // 32 KB: holds K tile, then V tile
    int tid = threadIdx.x;
    int i = tid >> 2;                     // 0..63 q-row in tile
    int c = tid & 3;                      // 0..3
    int qt = blockIdx.x;                  // 0..31 q tile
    int bh = blockIdx.y;                  // 0..31
    int b = bh >> 4, h = bh & (NH_ - 1);
    size_t base = (size_t)bh * S_ * HD_;
    int qg = qt * 64 + i;

    ull qf[16];
    {
        const float* qrow = g_q + base + (size_t)qg * HD_ + 2*c;
        ull sc2 = pack2(SCALE_);
#pragma unroll
        for (int t = 0; t < 16; t++)
            qf[t] = mul2(*(const ull*)(qrow + 8*t), sc2);
    }
    ull o[16];
#pragma unroll
    for (int t = 0; t < 16; t++) o[t] = 0ull;
    float mcur = -1e30f, l = 0.f;

    for (int kt = 0; kt <= qt; kt++) {
        const float* kptr = g_k + base + (size_t)kt * 64 * HD_;
        __syncthreads();
#pragma unroll
        for (int r = 0; r < 8; r++) {
            int f = tid + 256 * r;
            *(float4*)&Ts[f*4] = *(const float4*)(kptr + f*4);
        }
        __syncthreads();
        float s[64];
#pragma unroll
        for (int j = 0; j < 64; j++) {
            ull a = 0ull;
            const float* kr = &Ts[j*128 + 2*c];
#pragma unroll
            for (int t = 0; t < 16; t++) ffma2(a, qf[t], *(const ull*)(kr + 8*t));
            float lo, hi; unpack2(a, lo, hi);
            float p = lo + hi;
            p += __shfl_xor_sync(0xffffffffu, p, 1);
            p += __shfl_xor_sync(0xffffffffu, p, 2);
            s[j] = p;
        }
        if (kt == qt) {
#pragma unroll
            for (int j = 0; j < 64; j++) if (j > i) s[j] = -1e30f;
        }
        float mnew = mcur;
#pragma unroll
        for (int j = 0; j < 64; j++) mnew = fmaxf(mnew, s[j]);
        float corr = __expf(mcur - mnew);
        mcur = mnew;
        l *= corr;
        ull corr2 = pack2(corr);
#pragma unroll
        for (int t = 0; t < 16; t++) o[t] = mul2(o[t], corr2);
        const float* vptr = g_v + base + (size_t)kt * 64 * HD_;
        __syncthreads();
#pragma unroll
        for (int r = 0; r < 8; r++) {
            int f = tid + 256 * r;
            *(float4*)&Ts[f*4] = *(const float4*)(vptr + f*4);
        }
        __syncthreads();
#pragma unroll
        for (int j = 0; j < 64; j++) {
            float p = __expf(s[j] - mcur);
            l += p;
            ull p2 = pack2(p);
            const float* vr = &Ts[j*128 + 2*c];
#pragma unroll
            for (int t = 0; t < 16; t++) ffma2(o[t], p2, *(const ull*)(vr + 8*t));
        }
    }

    float inv = 1.f / l;
    float* orow = g_ctx + ((size_t)b * S_ + qg) * H_ + h * HD_ + 2*c;
#pragma unroll
    for (int t = 0; t < 16; t++) {
        float lo, hi; unpack2(o[t], lo, hi);
        *(float2*)(orow + 8*t) = make_float2(lo * inv, hi * inv);
    }
}

// ---------------- launch ---------------------------------------------------
extern "C" void kernel_launch(void* const* d_in, const int* in_sizes, int n_in,
                              void* d_out, int out_size)
{
    const float* X   = (const float*)d_in[0];
    const float* cp  = (const float*)d_in[1];
    const float* sp  = (const float*)d_in[2];
    const float* Wq  = (const float*)d_in[3];
    const float* Wk  = (const float*)d_in[4];
    const float* Wv  = (const float*)d_in[5];
    const float* Wo  = (const float*)d_in[6];
    float* out = (float*)d_out;

    k_qkv_tc<<<dim3(48, 32), 256>>>(X, Wq, Wk, Wv);

    int total = B_ * NH_ * S_ * 64;        // 4,194,304
    k_rope<<<total / 256, 256>>>(cp, sp);

    k_flash<<<dim3(S_ / 64, B_ * NH_), 256>>>();

    k_out_tc<<<dim3(16, 32), 256>>>(Wo, out);
}

// round 4
// speedup vs baseline: 3.8542x; 2.4630x over previous
#include <cuda_runtime.h>
#include <cuda_bf16.h>
#include <cstdint>

#define B_  2
#define S_  2048
#define H_  2048
#define NH_ 16
#define HD_ 128
#define M_  (B_*S_)            // 4096
#define SCALE_ 0.08838834764831845f   // 128^-0.5

// ---------------- scratch (device globals: no allocation allowed) ----------
__device__ float g_q[(size_t)B_*NH_*S_*HD_];     // [b,h,s,d] fp32
__device__ float g_k[(size_t)B_*NH_*S_*HD_];     // [b,h,s,d] tf32 bits (post-rope)
__device__ float g_v[(size_t)B_*NH_*S_*HD_];     // [b,h,s,d] tf32 bits
__device__ float g_ctx[(size_t)B_*S_*H_];        // [b,s,h*HD+d]

// ---------------- tf32 helpers ---------------------------------------------
__device__ __forceinline__ unsigned tf32_of(float f) {
    unsigned r; asm("cvt.rn.tf32.f32 %0, %1;" : "=r"(r) : "f"(f)); return r;
}
__device__ __forceinline__ uint4 cvt4(float4 v) {
    uint4 o; o.x = tf32_of(v.x); o.y = tf32_of(v.y); o.z = tf32_of(v.z); o.w = tf32_of(v.w);
    return o;
}
__device__ __forceinline__ void mma8(float* c, const unsigned* a, unsigned b0, unsigned b1) {
    asm volatile(
        "mma.sync.aligned.m16n8k8.row.col.f32.tf32.tf32.f32 "
        "{%0,%1,%2,%3}, {%4,%5,%6,%7}, {%8,%9}, {%0,%1,%2,%3};"
        : "+f"(c[0]), "+f"(c[1]), "+f"(c[2]), "+f"(c[3])
        : "r"(a[0]), "r"(a[1]), "r"(a[2]), "r"(a[3]), "r"(b0), "r"(b1));
}

// ======================= tf32 mma.sync GEMM ================================
// C[m,n] = sum_k A[m,k] * W[n,k]. CTA tile 128x128, BK=16, 256 threads.
// MODE 0: C[m*H_+n].  MODE 1: scatter [b,h,s,d] fp32.  MODE 2: scatter tf32.
#define BK  16
#define STR 20

template<int MODE>
__device__ __forceinline__ void gemm_tc(const float* __restrict__ A,
                                        const float* __restrict__ W,
                                        float* __restrict__ Cdst,
                                        int mb, int nb)
{
    __shared__ float As[2][128*STR];
    __shared__ float Bs[2][128*STR];

    const int tid = threadIdx.x;
    const int wid = tid >> 5, lane = tid & 31;
    const int g = lane >> 2, r = lane & 3;
    const int wm = (wid >> 2) * 64;
    const int wn = (wid & 3) * 32;

    float c[4][4][4];
#pragma unroll
    for (int i = 0; i < 4; i++)
#pragma unroll
        for (int j = 0; j < 4; j++)
#pragma unroll
            for (int q = 0; q < 4; q++) c[i][j][q] = 0.f;

    float4 ra[2], rb[2];
    {
#pragma unroll
        for (int q = 0; q < 2; q++) {
            int f = tid + 256*q; int row = f >> 2, kq = f & 3;
            ra[q] = *(const float4*)(A + (size_t)(mb + row)*H_ + kq*4);
            rb[q] = *(const float4*)(W + (size_t)(nb + row)*H_ + kq*4);
        }
#pragma unroll
        for (int q = 0; q < 2; q++) {
            int f = tid + 256*q; int row = f >> 2, kq = f & 3;
            *(uint4*)&As[0][row*STR + kq*4] = cvt4(ra[q]);
            *(uint4*)&Bs[0][row*STR + kq*4] = cvt4(rb[q]);
        }
    }
    __syncthreads();

    const int NCH = H_ / BK;
    for (int ch = 0; ch < NCH; ch++) {
        int buf = ch & 1;
        if (ch + 1 < NCH) {
            int kb = (ch + 1) * BK;
#pragma unroll
            for (int q = 0; q < 2; q++) {
                int f = tid + 256*q; int row = f >> 2, kq = f & 3;
                ra[q] = *(const float4*)(A + (size_t)(mb + row)*H_ + kb + kq*4);
                rb[q] = *(const float4*)(W + (size_t)(nb + row)*H_ + kb + kq*4);
            }
        }
        const float* as = As[buf];
        const float* bs = Bs[buf];
#pragma unroll
        for (int ks = 0; ks < 2; ks++) {
            unsigned af[4][4], bf[4][2];
#pragma unroll
            for (int mf = 0; mf < 4; mf++) {
                const unsigned* ap = (const unsigned*)&as[(wm + mf*16 + g)*STR + ks*8 + r];
                af[mf][0] = ap[0];
                af[mf][1] = ap[8*STR];
                af[mf][2] = ap[4];
                af[mf][3] = ap[8*STR + 4];
            }
#pragma unroll
            for (int nf = 0; nf < 4; nf++) {
                const unsigned* bp = (const unsigned*)&bs[(wn + nf*8 + g)*STR + ks*8 + r];
                bf[nf][0] = bp[0];
                bf[nf][1] = bp[4];
            }
#pragma unroll
            for (int mf = 0; mf < 4; mf++)
#pragma unroll
                for (int nf = 0; nf < 4; nf++)
                    mma8(c[mf][nf], af[mf], bf[nf][0], bf[nf][1]);
        }
        if (ch + 1 < NCH) {
#pragma unroll
            for (int q = 0; q < 2; q++) {
                int f = tid + 256*q; int row = f >> 2, kq = f & 3;
                *(uint4*)&As[buf ^ 1][row*STR + kq*4] = cvt4(ra[q]);
                *(uint4*)&Bs[buf ^ 1][row*STR + kq*4] = cvt4(rb[q]);
            }
            __syncthreads();
        }
    }

#pragma unroll
    for (int mf = 0; mf < 4; mf++) {
#pragma unroll
        for (int nf = 0; nf < 4; nf++) {
            int mrow = mb + wm + mf*16 + g;
            int col  = nb + wn + nf*8 + r*2;
#pragma unroll
            for (int half = 0; half < 2; half++) {
                int m = mrow + half*8;
                float2 v = make_float2(c[mf][nf][half*2], c[mf][nf][half*2 + 1]);
                if (MODE == 0) {
                    *(float2*)&Cdst[(size_t)m*H_ + col] = v;
                } else {
                    if (MODE == 2) {
                        v.x = __uint_as_float(tf32_of(v.x));
                        v.y = __uint_as_float(tf32_of(v.y));
                    }
                    int b = m >> 11, s = m & (S_ - 1);
                    int h = col >> 7, d0 = col & (HD_ - 1);
                    *(float2*)&Cdst[(((size_t)(b*NH_ + h))*S_ + s)*HD_ + d0] = v;
                }
            }
        }
    }
}

__global__ void __launch_bounds__(256) k_qk_tc(const float* __restrict__ X,
                                               const float* __restrict__ Wq,
                                               const float* __restrict__ Wk) {
    int which = blockIdx.x >> 4;                 // 0=q 1=k
    int nb = (blockIdx.x & 15) * 128;
    int mb = blockIdx.y * 128;
    gemm_tc<1>(X, which ? Wk : Wq, which ? g_k : g_q, mb, nb);
}
__global__ void __launch_bounds__(256) k_v_tc(const float* __restrict__ X,
                                              const float* __restrict__ Wv) {
    gemm_tc<2>(X, Wv, g_v, (int)blockIdx.y * 128, (int)blockIdx.x * 128);
}
__global__ void __launch_bounds__(256) k_out_tc(const float* __restrict__ Wo,
                                                float* __restrict__ C) {
    gemm_tc<0>(g_ctx, Wo, C, (int)blockIdx.y * 128, (int)blockIdx.x * 128);
}

// ---------------- RoPE (in place; K is rounded to tf32 bits) ---------------
__global__ void k_rope(const float* __restrict__ cosp, const float* __restrict__ sinp)
{
    int idx = blockIdx.x * blockDim.x + threadIdx.x;   // B*NH*S*64 threads
    int d  = idx & 63;
    int s  = (idx >> 6) & (S_ - 1);
    int bh = idx >> 17;
    size_t base = ((size_t)bh * S_ + s) * HD_;
    float c1 = cosp[s*HD_ + d],      s1 = sinp[s*HD_ + d];
    float c2 = cosp[s*HD_ + d + 64], s2 = sinp[s*HD_ + d + 64];
    float x1 = g_q[base + d], x2 = g_q[base + d + 64];
    g_q[base + d]      = x1*c1 - x2*s1;
    g_q[base + d + 64] = x2*c2 + x1*s2;
    x1 = g_k[base + d]; x2 = g_k[base + d + 64];
    g_k[base + d]      = __uint_as_float(tf32_of(x1*c1 - x2*s1));
    g_k[base + d + 64] = __uint_as_float(tf32_of(x2*c2 + x1*s2));
}

// ---------------- causal flash attention (tensor cores) --------------------
// 256 threads = 8 warps; warp w owns q-rows qt*128 + w*16 .. +15.
// K tile [64][132], V tile [64][136], per-warp P tile [16][68] — all
// fragment access patterns hit 32 distinct banks (strides 4, 8, 4 mod 32).
#define BQ   128
#define BKT  64
#define NQT  (S_/BQ)                      // 16
#define STRK 132
#define STRV 136
#define STRP 68
#define KS_OFF 0
#define VS_OFF (64*STRK)                  // 8448
#define PS_OFF (VS_OFF + 64*STRV)         // 17152
#define FLASH_SMEM_BYTES ((PS_OFF + 8*16*STRP)*4)   // 103424

__global__ void __launch_bounds__(256, 1) k_flash_tc()
{
    extern __shared__ float fsm[];
    const int tid = threadIdx.x;
    const int wid = tid >> 5, lane = tid & 31;
    const int g = lane >> 2, r = lane & 3;
    const int qt = (NQT - 1) - (int)blockIdx.x;      // longest tiles first
    const int bh = blockIdx.y;
    const int b = bh >> 4, h = bh & (NH_ - 1);
    const size_t base = (size_t)bh * S_ * HD_;
    const int qrow0 = qt*BQ + wid*16;

    // Q fragments: scaled + tf32, held in registers
    unsigned qa[16][4];
    {
        const float* qp = g_q + base + (size_t)qrow0 * HD_;
#pragma unroll
        for (int ks = 0; ks < 16; ks++) {
            qa[ks][0] = tf32_of(qp[(size_t)g*HD_     + ks*8 + r    ] * SCALE_);
            qa[ks][1] = tf32_of(qp[(size_t)(g+8)*HD_ + ks*8 + r    ] * SCALE_);
            qa[ks][2] = tf32_of(qp[(size_t)g*HD_     + ks*8 + r + 4] * SCALE_);
            qa[ks][3] = tf32_of(qp[(size_t)(g+8)*HD_ + ks*8 + r + 4] * SCALE_);
        }
    }

    float oc[16][4];
#pragma unroll
    for (int nf = 0; nf < 16; nf++)
#pragma unroll
        for (int e = 0; e < 4; e++) oc[nf][e] = 0.f;
    float m0 = -1e30f, m1 = -1e30f, l0 = 0.f, l1 = 0.f;

    float* Pw = fsm + PS_OFF + wid * (16*STRP);
    const int ntiles = 2*(qt + 1);

    for (int kt = 0; kt < ntiles; kt++) {
        const float* kp = g_k + base + (size_t)kt*BKT*HD_;
        const float* vp = g_v + base + (size_t)kt*BKT*HD_;
        __syncthreads();
#pragma unroll
        for (int it = 0; it < 8; it++) {
            int f = tid + 256*it;            // 0..2047
            int row = f >> 5, c4 = (f & 31) * 4;
            *(float4*)&fsm[KS_OFF + row*STRK + c4] = *(const float4*)(kp + row*HD_ + c4);
            *(float4*)&fsm[VS_OFF + row*STRV + c4] = *(const float4*)(vp + row*HD_ + c4);
        }
        __syncthreads();

        if (kt*BKT <= qrow0 + 15) {          // warp has unmasked keys in tile
            // ---- scores: S = Q K^T ----
            float sc[8][4];
#pragma unroll
            for (int nf = 0; nf < 8; nf++)
#pragma unroll
                for (int e = 0; e < 4; e++) sc[nf][e] = 0.f;
#pragma unroll
            for (int ks = 0; ks < 16; ks++) {
#pragma unroll
                for (int nf = 0; nf < 8; nf++) {
                    unsigned b0 = __float_as_uint(fsm[KS_OFF + (nf*8+g)*STRK + ks*8 + r]);
                    unsigned b1 = __float_as_uint(fsm[KS_OFF + (nf*8+g)*STRK + ks*8 + r + 4]);
                    mma8(sc[nf], qa[ks], b0, b1);
                }
            }
            // ---- causal mask (diagonal tiles only) ----
            if (kt*BKT + BKT - 1 > qrow0) {
#pragma unroll
                for (int nf = 0; nf < 8; nf++) {
                    int key0 = kt*BKT + nf*8 + 2*r;
                    if (key0     > qrow0 + g)     sc[nf][0] = -1e30f;
                    if (key0 + 1 > qrow0 + g)     sc[nf][1] = -1e30f;
                    if (key0     > qrow0 + g + 8) sc[nf][2] = -1e30f;
                    if (key0 + 1 > qrow0 + g + 8) sc[nf][3] = -1e30f;
                }
            }
            // ---- online softmax ----
            float mx0 = sc[0][0], mx1 = sc[0][2];
#pragma unroll
            for (int nf = 0; nf < 8; nf++) {
                mx0 = fmaxf(mx0, fmaxf(sc[nf][0], sc[nf][1]));
                mx1 = fmaxf(mx1, fmaxf(sc[nf][2], sc[nf][3]));
            }
            mx0 = fmaxf(mx0, __shfl_xor_sync(0xffffffffu, mx0, 1));
            mx0 = fmaxf(mx0, __shfl_xor_sync(0xffffffffu, mx0, 2));
            mx1 = fmaxf(mx1, __shfl_xor_sync(0xffffffffu, mx1, 1));
            mx1 = fmaxf(mx1, __shfl_xor_sync(0xffffffffu, mx1, 2));
            float mn0 = fmaxf(m0, mx0), mn1 = fmaxf(m1, mx1);
            float cr0 = __expf(m0 - mn0), cr1 = __expf(m1 - mn1);
            m0 = mn0; m1 = mn1;
            l0 *= cr0; l1 *= cr1;
#pragma unroll
            for (int nf = 0; nf < 16; nf++) {
                oc[nf][0] *= cr0; oc[nf][1] *= cr0;
                oc[nf][2] *= cr1; oc[nf][3] *= cr1;
            }
#pragma unroll
            for (int nf = 0; nf < 8; nf++) {
                float p0 = __expf(sc[nf][0] - mn0);
                float p1 = __expf(sc[nf][1] - mn0);
                float p2 = __expf(sc[nf][2] - mn1);
                float p3 = __expf(sc[nf][3] - mn1);
                l0 += p0 + p1; l1 += p2 + p3;
                *(uint2*)&Pw[g*STRP     + nf*8 + 2*r] = make_uint2(tf32_of(p0), tf32_of(p1));
                *(uint2*)&Pw[(g+8)*STRP + nf*8 + 2*r] = make_uint2(tf32_of(p2), tf32_of(p3));
            }
            __syncwarp();
            // ---- O += P V ----
#pragma unroll
            for (int ks = 0; ks < 8; ks++) {
                unsigned pa[4];
                pa[0] = __float_as_uint(Pw[g*STRP     + ks*8 + r]);
                pa[1] = __float_as_uint(Pw[(g+8)*STRP + ks*8 + r]);
                pa[2] = __float_as_uint(Pw[g*STRP     + ks*8 + r + 4]);
                pa[3] = __float_as_uint(Pw[(g+8)*STRP + ks*8 + r + 4]);
#pragma unroll
                for (int nf = 0; nf < 16; nf++) {
                    unsigned b0 = __float_as_uint(fsm[VS_OFF + (ks*8+r)*STRV   + nf*8 + g]);
                    unsigned b1 = __float_as_uint(fsm[VS_OFF + (ks*8+r+4)*STRV + nf*8 + g]);
                    mma8(oc[nf], pa, b0, b1);
                }
            }
            __syncwarp();
        }
    }

    l0 += __shfl_xor_sync(0xffffffffu, l0, 1);
    l0 += __shfl_xor_sync(0xffffffffu, l0, 2);
    l1 += __shfl_xor_sync(0xffffffffu, l1, 1);
    l1 += __shfl_xor_sync(0xffffffffu, l1, 2);
    float i0 = 1.f / l0, i1 = 1.f / l1;
    float* o0 = g_ctx + ((size_t)b*S_ + qrow0 + g    ) * H_ + h*HD_;
    float* o1 = g_ctx + ((size_t)b*S_ + qrow0 + g + 8) * H_ + h*HD_;
#pragma unroll
    for (int nf = 0; nf < 16; nf++) {
        *(float2*)&o0[nf*8 + 2*r] = make_float2(oc[nf][0]*i0, oc[nf][1]*i0);
        *(float2*)&o1[nf*8 + 2*r] = make_float2(oc[nf][2]*i1, oc[nf][3]*i1);
    }
}

// ---------------- launch ---------------------------------------------------
extern "C" void kernel_launch(void* const* d_in, const int* in_sizes, int n_in,
                              void* d_out, int out_size)
{
    const float* X   = (const float*)d_in[0];
    const float* cp  = (const float*)d_in[1];
    const float* sp  = (const float*)d_in[2];
    const float* Wq  = (const float*)d_in[3];
    const float* Wk  = (const float*)d_in[4];
    const float* Wv  = (const float*)d_in[5];
    const float* Wo  = (const float*)d_in[6];
    float* out = (float*)d_out;

    cudaFuncSetAttribute(k_flash_tc, cudaFuncAttributeMaxDynamicSharedMemorySize,
                         FLASH_SMEM_BYTES);

    k_qk_tc<<<dim3(32, 32), 256>>>(X, Wq, Wk);
    k_v_tc<<<dim3(16, 32), 256>>>(X, Wv);

    int total = B_ * NH_ * S_ * 64;        // 4,194,304
    k_rope<<<total / 256, 256>>>(cp, sp);

    k_flash_tc<<<dim3(NQT, B_*NH_), 256, FLASH_SMEM_BYTES>>>();

    k_out_tc<<<dim3(16, 32), 256>>>(Wo, out);
}

// round 5
// speedup vs baseline: 4.3741x; 1.1349x over previous
#include <cuda_runtime.h>
#include <cuda_bf16.h>
#include <cstdint>

#define B_  2
#define S_  2048
#define H_  2048
#define NH_ 16
#define HD_ 128
#define M_  (B_*S_)            // 4096
#define SCALE_ 0.08838834764831845f   // 128^-0.5

// ---------------- scratch (device globals: no allocation allowed) ----------
__device__ float g_q[(size_t)B_*NH_*S_*HD_];     // [b,h,s,d] fp32
__device__ float g_k[(size_t)B_*NH_*S_*HD_];     // [b,h,s,d] tf32 bits (post-rope)
__device__ float g_v[(size_t)B_*NH_*S_*HD_];     // [b,h,s,d] tf32 bits
__device__ float g_ctx[(size_t)B_*S_*H_];        // [b,s,h*HD+d] tf32 bits
__device__ float g_xc[(size_t)M_*H_];            // X  pre-rounded to tf32
__device__ float g_wq[(size_t)H_*H_];            // W* pre-rounded to tf32
__device__ float g_wk[(size_t)H_*H_];
__device__ float g_wv[(size_t)H_*H_];
__device__ float g_wo[(size_t)H_*H_];

// ---------------- tf32 helpers ---------------------------------------------
__device__ __forceinline__ unsigned tf32_of(float f) {
    unsigned r; asm("cvt.rn.tf32.f32 %0, %1;" : "=r"(r) : "f"(f)); return r;
}
__device__ __forceinline__ uint4 cvt4(float4 v) {
    uint4 o; o.x = tf32_of(v.x); o.y = tf32_of(v.y); o.z = tf32_of(v.z); o.w = tf32_of(v.w);
    return o;
}
__device__ __forceinline__ void mma8(float* c, const unsigned* a, unsigned b0, unsigned b1) {
    asm volatile(
        "mma.sync.aligned.m16n8k8.row.col.f32.tf32.tf32.f32 "
        "{%0,%1,%2,%3}, {%4,%5,%6,%7}, {%8,%9}, {%0,%1,%2,%3};"
        : "+f"(c[0]), "+f"(c[1]), "+f"(c[2]), "+f"(c[3])
        : "r"(a[0]), "r"(a[1]), "r"(a[2]), "r"(a[3]), "r"(b0), "r"(b1));
}
__device__ __forceinline__ uint32_t smem_u32(const void* p) {
    uint32_t a;
    asm("{ .reg .u64 t; cvta.to.shared.u64 t, %1; cvt.u32.u64 %0, t; }" : "=r"(a) : "l"(p));
    return a;
}
__device__ __forceinline__ void cp16(uint32_t saddr, const float* g) {
    asm volatile("cp.async.cg.shared.global [%0], [%1], 16;" :: "r"(saddr), "l"(g) : "memory");
}
#define CP_COMMIT() asm volatile("cp.async.commit_group;" ::: "memory")
#define CP_WAIT2()  asm volatile("cp.async.wait_group 2;" ::: "memory")

// ---------------- pre-conversion kernel ------------------------------------
__global__ void k_cvt(const float* __restrict__ src, float* __restrict__ dst) {
    int i = blockIdx.x * blockDim.x + threadIdx.x;
    float4 v = ((const float4*)src)[i];
    ((uint4*)dst)[i] = cvt4(v);
}

// ======================= tf32 mma.sync GEMM (cp.async) =====================
// C[m,n] = sum_k A[m,k]*W[n,k]; operands already tf32 bits. CTA 256x128,
// BK=16, 256 thr, 8 warps as 4(m)x2(n); warp tile 64x64 (mf=4, nf=8).
// Smem: 64B rows + SW128 xor swizzle; 4 async stages.
#define GM 256
#define GN 128
#define GK 16
#define NST 4
#define STAGE_W ((GM + GN) * GK)                  // floats per stage (6144)
#define GEMM_SMEM (NST * STAGE_W * 4)             // 98304 bytes

__device__ __forceinline__ int swz(int row, int col) {     // byte offset
    int off = row * 64 + col * 4;
    return off ^ ((off >> 3) & 0x70);
}

// MODE 0: C[m*H_+n]  MODE 1: scatter [b,h,s,d] fp32  MODE 2: scatter tf32
template<int MODE>
__device__ __forceinline__ void gemm_tc(const float* __restrict__ A,
                                        const float* __restrict__ W,
                                        float* __restrict__ Cdst,
                                        int mb, int nb)
{
    extern __shared__ float gsm[];
    const uint32_t sb = smem_u32(gsm);
    const int tid = threadIdx.x;
    const int wid = tid >> 5, lane = tid & 31;
    const int g = lane >> 2, r = lane & 3;
    const int wm = (wid >> 1) * 64;
    const int wn = (wid & 1) * 64;

    float c[4][8][4];
#pragma unroll
    for (int i = 0; i < 4; i++)
#pragma unroll
        for (int j = 0; j < 8; j++)
#pragma unroll
            for (int e = 0; e < 4; e++) c[i][j][e] = 0.f;

    const int lrow = tid >> 2, lslot = tid & 3;          // load mapping

    auto issue = [&](int ch) {
        uint32_t st = sb + (ch & (NST - 1)) * (STAGE_W * 4);
        const float* Ab = A + (size_t)mb * H_ + ch * GK;
        const float* Wb = W + (size_t)nb * H_ + ch * GK;
#pragma unroll
        for (int q = 0; q < 4; q++) {                    // A: 256 rows
            int row = lrow + 64 * q;
            cp16(st + swz(row, lslot * 4), Ab + (size_t)row * H_ + lslot * 4);
        }
        uint32_t stb = st + GM * GK * 4;
#pragma unroll
        for (int q = 0; q < 2; q++) {                    // B: 128 rows
            int row = lrow + 64 * q;
            cp16(stb + swz(row, lslot * 4), Wb + (size_t)row * H_ + lslot * 4);
        }
    };

    issue(0); CP_COMMIT();
    issue(1); CP_COMMIT();
    issue(2); CP_COMMIT();

    const int NCH = H_ / GK;                             // 128
    for (int ch = 0; ch < NCH; ch++) {
        CP_WAIT2();
        __syncthreads();
        if (ch + 3 < NCH) issue(ch + 3);
        CP_COMMIT();
        const char* as = (const char*)gsm + (ch & (NST - 1)) * (STAGE_W * 4);
        const char* bs = as + GM * GK * 4;
#pragma unroll
        for (int ks = 0; ks < 2; ks++) {
            unsigned bf[8][2];
#pragma unroll
            for (int nf = 0; nf < 8; nf++) {
                int row = wn + nf * 8 + g;
                bf[nf][0] = *(const unsigned*)(bs + swz(row, ks * 8 + r));
                bf[nf][1] = *(const unsigned*)(bs + swz(row, ks * 8 + r + 4));
            }
#pragma unroll
            for (int mf = 0; mf < 4; mf++) {
                unsigned af[4];
                int row = wm + mf * 16 + g;
                af[0] = *(const unsigned*)(as + swz(row,     ks * 8 + r));
                af[1] = *(const unsigned*)(as + swz(row + 8, ks * 8 + r));
                af[2] = *(const unsigned*)(as + swz(row,     ks * 8 + r + 4));
                af[3] = *(const unsigned*)(as + swz(row + 8, ks * 8 + r + 4));
#pragma unroll
                for (int nf = 0; nf < 8; nf++)
                    mma8(c[mf][nf], af, bf[nf][0], bf[nf][1]);
            }
        }
    }

    // epilogue
#pragma unroll
    for (int mf = 0; mf < 4; mf++) {
#pragma unroll
        for (int nf = 0; nf < 8; nf++) {
            int mrow = mb + wm + mf * 16 + g;
            int col  = nb + wn + nf * 8 + r * 2;
#pragma unroll
            for (int half = 0; half < 2; half++) {
                int m = mrow + half * 8;
                float2 v = make_float2(c[mf][nf][half * 2], c[mf][nf][half * 2 + 1]);
                if (MODE == 0) {
                    *(float2*)&Cdst[(size_t)m * H_ + col] = v;
                } else {
                    if (MODE == 2) {
                        v.x = __uint_as_float(tf32_of(v.x));
                        v.y = __uint_as_float(tf32_of(v.y));
                    }
                    int b = m >> 11, s = m & (S_ - 1);
                    int h = col >> 7, d0 = col & (HD_ - 1);
                    *(float2*)&Cdst[(((size_t)(b * NH_ + h)) * S_ + s) * HD_ + d0] = v;
                }
            }
        }
    }
}

__global__ void __launch_bounds__(256, 1) k_qkv_tc() {
    int which = blockIdx.x >> 4;                 // 0=q 1=k 2=v
    int nb = (blockIdx.x & 15) * GN;
    int mb = blockIdx.y * GM;
    if (which == 0)      gemm_tc<1>(g_xc, g_wq, g_q, mb, nb);
    else if (which == 1) gemm_tc<1>(g_xc, g_wk, g_k, mb, nb);
    else                 gemm_tc<2>(g_xc, g_wv, g_v, mb, nb);
}
__global__ void __launch_bounds__(256, 1) k_out_tc(float* __restrict__ C) {
    gemm_tc<0>(g_ctx, g_wo, C, (int)blockIdx.y * GM, (int)blockIdx.x * GN);
}

// ---------------- RoPE (in place; K is rounded to tf32 bits) ---------------
__global__ void k_rope(const float* __restrict__ cosp, const float* __restrict__ sinp)
{
    int idx = blockIdx.x * blockDim.x + threadIdx.x;   // B*NH*S*64 threads
    int d  = idx & 63;
    int s  = (idx >> 6) & (S_ - 1);
    int bh = idx >> 17;
    size_t base = ((size_t)bh * S_ + s) * HD_;
    float c1 = cosp[s*HD_ + d],      s1 = sinp[s*HD_ + d];
    float c2 = cosp[s*HD_ + d + 64], s2 = sinp[s*HD_ + d + 64];
    float x1 = g_q[base + d], x2 = g_q[base + d + 64];
    g_q[base + d]      = x1*c1 - x2*s1;
    g_q[base + d + 64] = x2*c2 + x1*s2;
    x1 = g_k[base + d]; x2 = g_k[base + d + 64];
    g_k[base + d]      = __uint_as_float(tf32_of(x1*c1 - x2*s1));
    g_k[base + d + 64] = __uint_as_float(tf32_of(x2*c2 + x1*s2));
}

// ---------------- causal flash attention (tensor cores) --------------------
#define BQ   128
#define BKT  64
#define NQT  (S_/BQ)                      // 16
#define STRK 132
#define STRV 136
#define STRP 68
#define KS_OFF 0
#define VS_OFF (64*STRK)                  // 8448
#define PS_OFF (VS_OFF + 64*STRV)         // 17152
#define FLASH_SMEM_BYTES ((PS_OFF + 8*16*STRP)*4)   // 103424

__global__ void __launch_bounds__(256, 1) k_flash_tc()
{
    extern __shared__ float fsm[];
    const int tid = threadIdx.x;
    const int wid = tid >> 5, lane = tid & 31;
    const int g = lane >> 2, r = lane & 3;
    const int qt = (NQT - 1) - (int)blockIdx.x;      // longest tiles first
    const int bh = blockIdx.y;
    const int b = bh >> 4, h = bh & (NH_ - 1);
    const size_t base = (size_t)bh * S_ * HD_;
    const int qrow0 = qt*BQ + wid*16;

    unsigned qa[16][4];
    {
        const float* qp = g_q + base + (size_t)qrow0 * HD_;
#pragma unroll
        for (int ks = 0; ks < 16; ks++) {
            qa[ks][0] = tf32_of(qp[(size_t)g*HD_     + ks*8 + r    ] * SCALE_);
            qa[ks][1] = tf32_of(qp[(size_t)(g+8)*HD_ + ks*8 + r    ] * SCALE_);
            qa[ks][2] = tf32_of(qp[(size_t)g*HD_     + ks*8 + r + 4] * SCALE_);
            qa[ks][3] = tf32_of(qp[(size_t)(g+8)*HD_ + ks*8 + r + 4] * SCALE_);
        }
    }

    float oc[16][4];
#pragma unroll
    for (int nf = 0; nf < 16; nf++)
#pragma unroll
        for (int e = 0; e < 4; e++) oc[nf][e] = 0.f;
    float m0 = -1e30f, m1 = -1e30f, l0 = 0.f, l1 = 0.f;

    float* Pw = fsm + PS_OFF + wid * (16*STRP);
    const int ntiles = 2*(qt + 1);

    for (int kt = 0; kt < ntiles; kt++) {
        const float* kp = g_k + base + (size_t)kt*BKT*HD_;
        const float* vp = g_v + base + (size_t)kt*BKT*HD_;
        __syncthreads();
#pragma unroll
        for (int it = 0; it < 8; it++) {
            int f = tid + 256*it;            // 0..2047
            int row = f >> 5, c4 = (f & 31) * 4;
            *(float4*)&fsm[KS_OFF + row*STRK + c4] = *(const float4*)(kp + row*HD_ + c4);
            *(float4*)&fsm[VS_OFF + row*STRV + c4] = *(const float4*)(vp + row*HD_ + c4);
        }
        __syncthreads();

        if (kt*BKT <= qrow0 + 15) {
            float sc[8][4];
#pragma unroll
            for (int nf = 0; nf < 8; nf++)
#pragma unroll
                for (int e = 0; e < 4; e++) sc[nf][e] = 0.f;
#pragma unroll
            for (int ks = 0; ks < 16; ks++) {
#pragma unroll
                for (int nf = 0; nf < 8; nf++) {
                    unsigned b0 = __float_as_uint(fsm[KS_OFF + (nf*8+g)*STRK + ks*8 + r]);
                    unsigned b1 = __float_as_uint(fsm[KS_OFF + (nf*8+g)*STRK + ks*8 + r + 4]);
                    mma8(sc[nf], qa[ks], b0, b1);
                }
            }
            if (kt*BKT + BKT - 1 > qrow0) {
#pragma unroll
                for (int nf = 0; nf < 8; nf++) {
                    int key0 = kt*BKT + nf*8 + 2*r;
                    if (key0     > qrow0 + g)     sc[nf][0] = -1e30f;
                    if (key0 + 1 > qrow0 + g)     sc[nf][1] = -1e30f;
                    if (key0     > qrow0 + g + 8) sc[nf][2] = -1e30f;
                    if (key0 + 1 > qrow0 + g + 8) sc[nf][3] = -1e30f;
                }
            }
            float mx0 = sc[0][0], mx1 = sc[0][2];
#pragma unroll
            for (int nf = 0; nf < 8; nf++) {
                mx0 = fmaxf(mx0, fmaxf(sc[nf][0], sc[nf][1]));
                mx1 = fmaxf(mx1, fmaxf(sc[nf][2], sc[nf][3]));
            }
            mx0 = fmaxf(mx0, __shfl_xor_sync(0xffffffffu, mx0, 1));
            mx0 = fmaxf(mx0, __shfl_xor_sync(0xffffffffu, mx0, 2));
            mx1 = fmaxf(mx1, __shfl_xor_sync(0xffffffffu, mx1, 1));
            mx1 = fmaxf(mx1, __shfl_xor_sync(0xffffffffu, mx1, 2));
            float mn0 = fmaxf(m0, mx0), mn1 = fmaxf(m1, mx1);
            float cr0 = __expf(m0 - mn0), cr1 = __expf(m1 - mn1);
            m0 = mn0; m1 = mn1;
            l0 *= cr0; l1 *= cr1;
#pragma unroll
            for (int nf = 0; nf < 16; nf++) {
                oc[nf][0] *= cr0; oc[nf][1] *= cr0;
                oc[nf][2] *= cr1; oc[nf][3] *= cr1;
            }
#pragma unroll
            for (int nf = 0; nf < 8; nf++) {
                float p0 = __expf(sc[nf][0] - mn0);
                float p1 = __expf(sc[nf][1] - mn0);
                float p2 = __expf(sc[nf][2] - mn1);
                float p3 = __expf(sc[nf][3] - mn1);
                l0 += p0 + p1; l1 += p2 + p3;
                *(uint2*)&Pw[g*STRP     + nf*8 + 2*r] = make_uint2(tf32_of(p0), tf32_of(p1));
                *(uint2*)&Pw[(g+8)*STRP + nf*8 + 2*r] = make_uint2(tf32_of(p2), tf32_of(p3));
            }
            __syncwarp();
#pragma unroll
            for (int ks = 0; ks < 8; ks++) {
                unsigned pa[4];
                pa[0] = __float_as_uint(Pw[g*STRP     + ks*8 + r]);
                pa[1] = __float_as_uint(Pw[(g+8)*STRP + ks*8 + r]);
                pa[2] = __float_as_uint(Pw[g*STRP     + ks*8 + r + 4]);
                pa[3] = __float_as_uint(Pw[(g+8)*STRP + ks*8 + r + 4]);
#pragma unroll
                for (int nf = 0; nf < 16; nf++) {
                    unsigned b0 = __float_as_uint(fsm[VS_OFF + (ks*8+r)*STRV   + nf*8 + g]);
                    unsigned b1 = __float_as_uint(fsm[VS_OFF + (ks*8+r+4)*STRV + nf*8 + g]);
                    mma8(oc[nf], pa, b0, b1);
                }
            }
            __syncwarp();
        }
    }

    l0 += __shfl_xor_sync(0xffffffffu, l0, 1);
    l0 += __shfl_xor_sync(0xffffffffu, l0, 2);
    l1 += __shfl_xor_sync(0xffffffffu, l1, 1);
    l1 += __shfl_xor_sync(0xffffffffu, l1, 2);
    float i0 = 1.f / l0, i1 = 1.f / l1;
    float* o0 = g_ctx + ((size_t)b*S_ + qrow0 + g    ) * H_ + h*HD_;
    float* o1 = g_ctx + ((size_t)b*S_ + qrow0 + g + 8) * H_ + h*HD_;
#pragma unroll
    for (int nf = 0; nf < 16; nf++) {
        *(uint2*)&o0[nf*8 + 2*r] = make_uint2(tf32_of(oc[nf][0]*i0), tf32_of(oc[nf][1]*i0));
        *(uint2*)&o1[nf*8 + 2*r] = make_uint2(tf32_of(oc[nf][2]*i1), tf32_of(oc[nf][3]*i1));
    }
}

// ---------------- launch ---------------------------------------------------
extern "C" void kernel_launch(void* const* d_in, const int* in_sizes, int n_in,
                              void* d_out, int out_size)
{
    const float* X   = (const float*)d_in[0];
    const float* cp  = (const float*)d_in[1];
    const float* sp  = (const float*)d_in[2];
    const float* Wq  = (const float*)d_in[3];
    const float* Wk  = (const float*)d_in[4];
    const float* Wv  = (const float*)d_in[5];
    const float* Wo  = (const float*)d_in[6];
    float* out = (float*)d_out;

    cudaFuncSetAttribute(k_flash_tc, cudaFuncAttributeMaxDynamicSharedMemorySize,
                         FLASH_SMEM_BYTES);
    cudaFuncSetAttribute(k_qkv_tc, cudaFuncAttributeMaxDynamicSharedMemorySize,
                         GEMM_SMEM);
    cudaFuncSetAttribute(k_out_tc, cudaFuncAttributeMaxDynamicSharedMemorySize,
                         GEMM_SMEM);

    float* g_xc_p, *g_wq_p, *g_wk_p, *g_wv_p, *g_wo_p;
    cudaGetSymbolAddress((void**)&g_xc_p, g_xc);
    cudaGetSymbolAddress((void**)&g_wq_p, g_wq);
    cudaGetSymbolAddress((void**)&g_wk_p, g_wk);
    cudaGetSymbolAddress((void**)&g_wv_p, g_wv);
    cudaGetSymbolAddress((void**)&g_wo_p, g_wo);

    k_cvt<<<(M_*H_/4)/256, 256>>>(X,  g_xc_p);
    k_cvt<<<(H_*H_/4)/256, 256>>>(Wq, g_wq_p);
    k_cvt<<<(H_*H_/4)/256, 256>>>(Wk, g_wk_p);
    k_cvt<<<(H_*H_/4)/256, 256>>>(Wv, g_wv_p);
    k_cvt<<<(H_*H_/4)/256, 256>>>(Wo, g_wo_p);

    k_qkv_tc<<<dim3(48, M_/GM), 256, GEMM_SMEM>>>();

    int total = B_ * NH_ * S_ * 64;        // 4,194,304
    k_rope<<<total / 256, 256>>>(cp, sp);

    k_flash_tc<<<dim3(NQT, B_*NH_), 256, FLASH_SMEM_BYTES>>>();

    k_out_tc<<<dim3(H_/GN, M_/GM), 256, GEMM_SMEM>>>(out);
}